// round 16
// baseline (speedup 1.0000x reference)
#include <cuda_runtime.h>
#include <cstdint>

#define NF 40
#define NP 780        // 40*39/2
#define ED 64
#define AS 32
#define THREADS 256
#define CP 128
#define NCH 7
#define NPAD (NCH*CP) // 896

#define XP 72         // xs pitch (f32): 16B-aligned rows
#define WP 40         // W tile pitch (40 % 32 == 8)
#define SP 40         // S pitch
#define YP 66         // Y pitch

// ---- dynamic smem byte offsets ----
#define XS_OFF    0        // xs [40][72] f32      11520
#define WB_OFF    11520    // W tf32 [64][40]      10240
#define OFFS_OFF  21760    // [896] u32             3584
#define PART_OFF  25344    // [896][2] f32          7168
#define LOG_OFF   32512    // [896] f32             3584
#define S_OFF     36096    // S [48][40] f32        7680
#define Y_OFF     43776    // Y [40][66] f32       10560
#define P4_OFF    54336    // [4][64] f32           1024
#define AB_OFF    55360    // 32 f32
#define PW_OFF    55488    // 32 f32
#define FW_OFF    55616    // 64 f32
#define RMAX_OFF  55872    // 8 f32
#define RSUM_OFF  55904    // 8 f32
#define RED_OFF   55936    // 64 f32
#define SMEM_TOTAL 56192   // x3 CTAs fits

__device__ __forceinline__ uint32_t tf32_of(float v) {
    uint32_t r; asm("cvt.rna.tf32.f32 %0, %1;" : "=r"(r) : "f"(v)); return r;
}

__device__ __forceinline__ void mma8(float& c0, float& c1, float& c2, float& c3,
                                     uint32_t a0, uint32_t a1, uint32_t a2, uint32_t a3,
                                     uint32_t b0, uint32_t b1) {
    asm("mma.sync.aligned.m16n8k8.row.col.f32.tf32.tf32.f32 "
        "{%0,%1,%2,%3}, {%4,%5,%6,%7}, {%8,%9}, {%0,%1,%2,%3};"
        : "+f"(c0), "+f"(c1), "+f"(c2), "+f"(c3)
        : "r"(a0), "r"(a1), "r"(a2), "r"(a3), "r"(b0), "r"(b1));
}

// closed-form triangular index inverse: returns i, sets rs = rowstart(i).
__device__ __forceinline__ int row_of(int p, int& rs) {
    int i = (int)((79.0f - sqrtf((float)(6241 - 8 * p))) * 0.5f);
    rs = i * (79 - i) / 2;
    if (p < rs) { --i; rs = i * (79 - i) / 2; }
    else if (p - rs >= 39 - i) { rs += 39 - i; ++i; }
    return i;
}

__global__ __launch_bounds__(THREADS, 3) void afm_kernel(
    const float* __restrict__ x,
    const float* __restrict__ attn_w,
    const float* __restrict__ attn_b,
    const float* __restrict__ proj_w,
    const float* __restrict__ proj_b,
    const float* __restrict__ fc_w,
    const float* __restrict__ fc_b,
    float* __restrict__ out)
{
    extern __shared__ char smem[];
    float* xs        = (float*)(smem + XS_OFF);
    float* logits_s  = (float*)(smem + LOG_OFF);
    float* part      = (float*)(smem + PART_OFF);
    float* Sm        = (float*)(smem + S_OFF);
    float* Ym        = (float*)(smem + Y_OFF);
    float* p4        = (float*)(smem + P4_OFF);
    float* ab_s      = (float*)(smem + AB_OFF);
    float* pw_s      = (float*)(smem + PW_OFF);
    float* fw_s      = (float*)(smem + FW_OFF);
    float* rmax      = (float*)(smem + RMAX_OFF);
    float* rsum      = (float*)(smem + RSUM_OFF);
    float* red_s     = (float*)(smem + RED_OFF);
    uint32_t* offs   = (uint32_t*)(smem + OFFS_OFF);
    uint32_t* WBu    = (uint32_t*)(smem + WB_OFF);

    const int tid  = threadIdx.x;
    const int lane = tid & 31;
    const int wid  = tid >> 5;
    const int b    = blockIdx.x;

    // ---- Phase 1: stage inputs ----
    const float* xb = x + (long long)b * (NF * ED);
    for (int idx = tid; idx < NF * ED; idx += THREADS)
        xs[(idx >> 6) * XP + (idx & 63)] = xb[idx];

    for (int e = tid; e < ED * AS; e += THREADS) {
        int d = e >> 5, n = e & 31;
        WBu[d * WP + n] = tf32_of(attn_w[e]);
    }

    if (tid < AS) { pw_s[tid] = proj_w[tid]; ab_s[tid] = attn_b[tid]; }
    if (tid < ED) fw_s[tid] = fc_w[tid];

    for (int p = tid; p < NPAD; p += THREADS) {
        uint32_t o = 0;
        if (p < NP) {
            int rs;
            int i = row_of(p, rs);
            int j = i + 1 + (p - rs);
            o = (uint32_t)(i * (XP * 4)) | ((uint32_t)(j * (XP * 4)) << 16);
        }
        offs[p] = o;
    }
    const float pb = proj_b[0];
    __syncthreads();

    const int kd   = lane & 3;
    const int qr   = lane >> 2;
    const int mgrp = wid & 3;
    const int ngrp = wid >> 2;

    // ---- hoist B fragments, K-quad permutation (validated in R13):
    // kt-pair P: thread kd owns dims d0 = 16P+4kd+{0,1,2,3};
    // kt=2P slots (kd,kd+4) = dims {d0, d0+1}; kt=2P+1 = {d0+2, d0+3}.
    uint32_t Bb[8][2][2];
#pragma unroll
    for (int P = 0; P < 4; ++P) {
#pragma unroll
        for (int nt = 0; nt < 2; ++nt) {
            const int nc = ngrp * 16 + nt * 8 + qr;
            const int d0 = P * 16 + kd * 4;
            Bb[2 * P][nt][0]     = WBu[(d0 + 0) * WP + nc];
            Bb[2 * P][nt][1]     = WBu[(d0 + 1) * WP + nc];
            Bb[2 * P + 1][nt][0] = WBu[(d0 + 2) * WP + nc];
            Bb[2 * P + 1][nt][1] = WBu[(d0 + 3) * WP + nc];
        }
    }

    float bia[2][2], pww[2][2];
#pragma unroll
    for (int nt = 0; nt < 2; ++nt) {
        const int c0 = ngrp * 16 + nt * 8 + kd * 2;
        bia[nt][0] = ab_s[c0];     bia[nt][1] = ab_s[c0 + 1];
        pww[nt][0] = pw_s[c0];     pww[nt][1] = pw_s[c0 + 1];
    }

    const char* xsc = (const char*)xs;

    // ---- Phase 2: barrier-free chunked tf32 MMA; float4 A-loads (K-quads) ----
    for (int t = 0; t < NCH; ++t) {
        const int pb0 = t * CP + mgrp * 32 + qr;
        const uint32_t oA = offs[pb0];        // mt0, row qr
        const uint32_t oB = offs[pb0 + 8];    // mt0, row qr+8
        const uint32_t oC = offs[pb0 + 16];   // mt1, row qr
        const uint32_t oD = offs[pb0 + 24];   // mt1, row qr+8
        const char* xiA = xsc + (oA & 0xffffu); const char* xjA = xsc + (oA >> 16);
        const char* xiB = xsc + (oB & 0xffffu); const char* xjB = xsc + (oB >> 16);
        const char* xiC = xsc + (oC & 0xffffu); const char* xjC = xsc + (oC >> 16);
        const char* xiD = xsc + (oD & 0xffffu); const char* xjD = xsc + (oD >> 16);

        float acc[2][2][4];
#pragma unroll
        for (int mt = 0; mt < 2; ++mt)
#pragma unroll
            for (int nt = 0; nt < 2; ++nt) {
                acc[mt][nt][0] = bia[nt][0];
                acc[mt][nt][1] = bia[nt][1];
                acc[mt][nt][2] = bia[nt][0];
                acc[mt][nt][3] = bia[nt][1];
            }

#pragma unroll
        for (int P = 0; P < 4; ++P) {
            const int db = P * 64 + kd * 16;   // byte offset of this thread's K-quad
            // ---- mt = 0 ----
            {
                const float4 iA = *(const float4*)(xiA + db);
                const float4 jA = *(const float4*)(xjA + db);
                const float4 iB = *(const float4*)(xiB + db);
                const float4 jB = *(const float4*)(xjB + db);
                // kt = 2P : dims d0, d0+1
                uint32_t a0 = __float_as_uint(iA.x * jA.x);
                uint32_t a2 = __float_as_uint(iA.y * jA.y);
                uint32_t a1 = __float_as_uint(iB.x * jB.x);
                uint32_t a3 = __float_as_uint(iB.y * jB.y);
                mma8(acc[0][0][0], acc[0][0][1], acc[0][0][2], acc[0][0][3],
                     a0, a1, a2, a3, Bb[2 * P][0][0], Bb[2 * P][0][1]);
                mma8(acc[0][1][0], acc[0][1][1], acc[0][1][2], acc[0][1][3],
                     a0, a1, a2, a3, Bb[2 * P][1][0], Bb[2 * P][1][1]);
                // kt = 2P+1 : dims d0+2, d0+3
                uint32_t c0 = __float_as_uint(iA.z * jA.z);
                uint32_t c2 = __float_as_uint(iA.w * jA.w);
                uint32_t c1 = __float_as_uint(iB.z * jB.z);
                uint32_t c3 = __float_as_uint(iB.w * jB.w);
                mma8(acc[0][0][0], acc[0][0][1], acc[0][0][2], acc[0][0][3],
                     c0, c1, c2, c3, Bb[2 * P + 1][0][0], Bb[2 * P + 1][0][1]);
                mma8(acc[0][1][0], acc[0][1][1], acc[0][1][2], acc[0][1][3],
                     c0, c1, c2, c3, Bb[2 * P + 1][1][0], Bb[2 * P + 1][1][1]);
            }
            // ---- mt = 1 ----
            {
                const float4 iC = *(const float4*)(xiC + db);
                const float4 jC = *(const float4*)(xjC + db);
                const float4 iD = *(const float4*)(xiD + db);
                const float4 jD = *(const float4*)(xjD + db);
                uint32_t a0 = __float_as_uint(iC.x * jC.x);
                uint32_t a2 = __float_as_uint(iC.y * jC.y);
                uint32_t a1 = __float_as_uint(iD.x * jD.x);
                uint32_t a3 = __float_as_uint(iD.y * jD.y);
                mma8(acc[1][0][0], acc[1][0][1], acc[1][0][2], acc[1][0][3],
                     a0, a1, a2, a3, Bb[2 * P][0][0], Bb[2 * P][0][1]);
                mma8(acc[1][1][0], acc[1][1][1], acc[1][1][2], acc[1][1][3],
                     a0, a1, a2, a3, Bb[2 * P][1][0], Bb[2 * P][1][1]);
                uint32_t c0 = __float_as_uint(iC.z * jC.z);
                uint32_t c2 = __float_as_uint(iC.w * jC.w);
                uint32_t c1 = __float_as_uint(iD.z * jD.z);
                uint32_t c3 = __float_as_uint(iD.w * jD.w);
                mma8(acc[1][0][0], acc[1][0][1], acc[1][0][2], acc[1][0][3],
                     c0, c1, c2, c3, Bb[2 * P + 1][0][0], Bb[2 * P + 1][0][1]);
                mma8(acc[1][1][0], acc[1][1][1], acc[1][1][2], acc[1][1][3],
                     c0, c1, c2, c3, Bb[2 * P + 1][1][0], Bb[2 * P + 1][1][1]);
            }
        }

#pragma unroll
        for (int mt = 0; mt < 2; ++mt) {
            float lp0 = 0.f, lp1 = 0.f;
#pragma unroll
            for (int nt = 0; nt < 2; ++nt) {
                lp0 += fmaxf(acc[mt][nt][0], 0.f) * pww[nt][0] + fmaxf(acc[mt][nt][1], 0.f) * pww[nt][1];
                lp1 += fmaxf(acc[mt][nt][2], 0.f) * pww[nt][0] + fmaxf(acc[mt][nt][3], 0.f) * pww[nt][1];
            }
            lp0 += __shfl_xor_sync(0xffffffffu, lp0, 1);
            lp0 += __shfl_xor_sync(0xffffffffu, lp0, 2);
            lp1 += __shfl_xor_sync(0xffffffffu, lp1, 1);
            lp1 += __shfl_xor_sync(0xffffffffu, lp1, 2);
            if (kd == 0) {
                const int p0 = pb0 + mt * 16;
                part[p0 * 2 + ngrp]       = lp0;
                part[(p0 + 8) * 2 + ngrp] = lp1;
            }
        }
    }

    // zero S (48x40)
    {
        uint4 z = make_uint4(0, 0, 0, 0);
        uint4* S4 = (uint4*)Sm;
        for (int idx = tid; idx < 48 * SP / 4; idx += THREADS) S4[idx] = z;
    }
    __syncthreads();

    // ---- Phase 3: softmax (max, exp + scatter into symmetric S) ----
    float lm = -3.4e38f;
    for (int p = tid; p < NP; p += THREADS) {
        float lg = part[p * 2] + part[p * 2 + 1] + pb;
        logits_s[p] = lg;
        lm = fmaxf(lm, lg);
    }
#pragma unroll
    for (int o = 16; o > 0; o >>= 1) lm = fmaxf(lm, __shfl_xor_sync(0xffffffffu, lm, o));
    if (lane == 0) rmax[wid] = lm;
    __syncthreads();

    float gmax = rmax[0];
#pragma unroll
    for (int wq = 1; wq < 8; ++wq) gmax = fmaxf(gmax, rmax[wq]);

    float ls = 0.f;
    for (int p = tid; p < NP; p += THREADS) {
        float e = __expf(logits_s[p] - gmax);
        ls += e;
        int rs;
        int i = row_of(p, rs);
        int j = i + 1 + (p - rs);
        float et = __uint_as_float(tf32_of(e));
        Sm[i * SP + j] = et;
        Sm[j * SP + i] = et;
    }
#pragma unroll
    for (int o = 16; o > 0; o >>= 1) ls += __shfl_xor_sync(0xffffffffu, ls, o);
    if (lane == 0) rsum[wid] = ls;
    __syncthreads();

    // ---- Phase 4: Y = S @ X via MMA; warp w = ntile w (8 dims) ----
    {
        const int w = wid;
        const int nc = w * 8 + qr;
        uint32_t Bx[5][2];
#pragma unroll
        for (int kt = 0; kt < 5; ++kt) {
            const int k0 = kt * 8 + kd * 2;
            Bx[kt][0] = tf32_of(xs[k0 * XP + nc]);
            Bx[kt][1] = tf32_of(xs[(k0 + 1) * XP + nc]);
        }
#pragma unroll
        for (int mt = 0; mt < 3; ++mt) {
            float c0 = 0.f, c1 = 0.f, c2 = 0.f, c3 = 0.f;
            const int row = mt * 16 + qr;
#pragma unroll
            for (int kt = 0; kt < 5; ++kt) {
                const int k0 = kt * 8 + kd * 2;
                const float2 sA = *(const float2*)(Sm + row * SP + k0);
                const float2 sB = *(const float2*)(Sm + (row + 8) * SP + k0);
                mma8(c0, c1, c2, c3,
                     __float_as_uint(sA.x), __float_as_uint(sB.x),
                     __float_as_uint(sA.y), __float_as_uint(sB.y),
                     Bx[kt][0], Bx[kt][1]);
            }
            *(float2*)(Ym + row * YP + w * 8 + kd * 2) = make_float2(c0, c1);
            if (mt < 2)
                *(float2*)(Ym + (row + 8) * YP + w * 8 + kd * 2) = make_float2(c2, c3);
        }
    }
    __syncthreads();

    // ---- final: attn_out[d] = 0.5 * sum_i x_i[d]*Y[i][d]; dot fc_w; /S ----
    {
        const int d = tid & 63;
        const int q = tid >> 6;
        float pa = 0.f;
#pragma unroll
        for (int i = q * 10; i < q * 10 + 10; ++i)
            pa += xs[i * XP + d] * Ym[i * YP + d];
        p4[q * 64 + d] = pa;
    }
    __syncthreads();

    if (tid < 64) {
        float v = p4[tid] + p4[64 + tid] + p4[128 + tid] + p4[192 + tid];
        red_s[tid] = 0.5f * v * fw_s[tid];
    }
    __syncthreads();

    if (tid == 0) {
        float S = 0.f;
#pragma unroll
        for (int wq = 0; wq < 8; ++wq) S += rsum[wq];
        float tt = 0.f;
#pragma unroll
        for (int k = 0; k < 64; ++k) tt += red_s[k];
        out[b] = tt / S + fc_b[0];
    }
}

extern "C" void kernel_launch(void* const* d_in, const int* in_sizes, int n_in,
                              void* d_out, int out_size)
{
    const float* x      = (const float*)d_in[0];
    const float* attn_w = (const float*)d_in[1];
    const float* attn_b = (const float*)d_in[2];
    const float* proj_w = (const float*)d_in[3];
    const float* proj_b = (const float*)d_in[4];
    const float* fc_w   = (const float*)d_in[5];
    const float* fc_b   = (const float*)d_in[6];
    float* out = (float*)d_out;

    cudaFuncSetAttribute(afm_kernel, cudaFuncAttributeMaxDynamicSharedMemorySize, SMEM_TOTAL);
    afm_kernel<<<2048, THREADS, SMEM_TOTAL>>>(x, attn_w, attn_b, proj_w, proj_b, fc_w, fc_b, out);
}

// round 17
// speedup vs baseline: 1.4359x; 1.4359x over previous
#include <cuda_runtime.h>
#include <cstdint>

#define NF 40
#define NP 780        // 40*39/2
#define ED 64
#define AS 32
#define THREADS 256
#define CP 128
#define NCH 7
#define NPAD (NCH*CP) // 896

#define XP 72         // xs pitch (f32)
#define WP 40         // W tile pitch (40 % 32 == 8)
#define SP 40         // S pitch
#define YP 66         // Y pitch

// ---- dynamic smem byte offsets ----
#define XS_OFF    0        // xs [40][72] f32      11520
#define WB_OFF    11520    // W tf32 [64][40]      10240
#define OFFS_OFF  21760    // [896] u32             3584
#define PART_OFF  25344    // [896][2] f32          7168
#define LOG_OFF   32512    // [896] f32             3584
#define S_OFF     36096    // S [48][40] f32        7680
#define Y_OFF     43776    // Y [40][66] f32       10560
#define P4_OFF    54336    // [4][64] f32           1024
#define AB_OFF    55360    // 32 f32
#define PW_OFF    55488    // 32 f32
#define FW_OFF    55616    // 64 f32
#define RMAX_OFF  55872    // 8 f32
#define RSUM_OFF  55904    // 8 f32
#define RED_OFF   55936    // 64 f32
#define SMEM_TOTAL 56192

__device__ __forceinline__ uint32_t tf32_of(float v) {
    uint32_t r; asm("cvt.rna.tf32.f32 %0, %1;" : "=r"(r) : "f"(v)); return r;
}

__device__ __forceinline__ void mma8(float& c0, float& c1, float& c2, float& c3,
                                     uint32_t a0, uint32_t a1, uint32_t a2, uint32_t a3,
                                     uint32_t b0, uint32_t b1) {
    asm("mma.sync.aligned.m16n8k8.row.col.f32.tf32.tf32.f32 "
        "{%0,%1,%2,%3}, {%4,%5,%6,%7}, {%8,%9}, {%0,%1,%2,%3};"
        : "+f"(c0), "+f"(c1), "+f"(c2), "+f"(c3)
        : "r"(a0), "r"(a1), "r"(a2), "r"(a3), "r"(b0), "r"(b1));
}

// closed-form triangular index inverse: returns i, sets rs = rowstart(i).
__device__ __forceinline__ int row_of(int p, int& rs) {
    int i = (int)((79.0f - sqrtf((float)(6241 - 8 * p))) * 0.5f);
    rs = i * (79 - i) / 2;
    if (p < rs) { --i; rs = i * (79 - i) / 2; }
    else if (p - rs >= 39 - i) { rs += 39 - i; ++i; }
    return i;
}

__global__ __launch_bounds__(THREADS, 3) void afm_kernel(
    const float* __restrict__ x,
    const float* __restrict__ attn_w,
    const float* __restrict__ attn_b,
    const float* __restrict__ proj_w,
    const float* __restrict__ proj_b,
    const float* __restrict__ fc_w,
    const float* __restrict__ fc_b,
    float* __restrict__ out)
{
    extern __shared__ char smem[];
    float* xs        = (float*)(smem + XS_OFF);
    float* logits_s  = (float*)(smem + LOG_OFF);
    float* part      = (float*)(smem + PART_OFF);
    float* Sm        = (float*)(smem + S_OFF);
    float* Ym        = (float*)(smem + Y_OFF);
    float* p4        = (float*)(smem + P4_OFF);
    float* ab_s      = (float*)(smem + AB_OFF);
    float* pw_s      = (float*)(smem + PW_OFF);
    float* fw_s      = (float*)(smem + FW_OFF);
    float* rmax      = (float*)(smem + RMAX_OFF);
    float* rsum      = (float*)(smem + RSUM_OFF);
    float* red_s     = (float*)(smem + RED_OFF);
    uint32_t* offs   = (uint32_t*)(smem + OFFS_OFF);
    uint32_t* WBu    = (uint32_t*)(smem + WB_OFF);

    const int tid  = threadIdx.x;
    const int lane = tid & 31;
    const int wid  = tid >> 5;
    const int b    = blockIdx.x;

    // ---- Phase 1: stage inputs ----
    const float* xb = x + (long long)b * (NF * ED);
    for (int idx = tid; idx < NF * ED; idx += THREADS)
        xs[(idx >> 6) * XP + (idx & 63)] = xb[idx];

    for (int e = tid; e < ED * AS; e += THREADS) {
        int d = e >> 5, n = e & 31;
        WBu[d * WP + n] = tf32_of(attn_w[e]);
    }

    if (tid < AS) { pw_s[tid] = proj_w[tid]; ab_s[tid] = attn_b[tid]; }
    if (tid < ED) fw_s[tid] = fc_w[tid];

    for (int p = tid; p < NPAD; p += THREADS) {
        uint32_t o = 0;
        if (p < NP) {
            int rs;
            int i = row_of(p, rs);
            int j = i + 1 + (p - rs);
            o = (uint32_t)(i * (XP * 4)) | ((uint32_t)(j * (XP * 4)) << 16);
        }
        offs[p] = o;
    }
    const float pb = proj_b[0];
    __syncthreads();

    const int kd   = lane & 3;
    const int qr   = lane >> 2;
    const int mgrp = wid & 3;
    const int ngrp = wid >> 2;

    // ---- hoist B fragments (K-permuted: slots kd,kd+4 -> d = 8kt+2kd, +1) ----
    uint32_t Bb[8][2][2];
#pragma unroll
    for (int kt = 0; kt < 8; ++kt) {
#pragma unroll
        for (int nt = 0; nt < 2; ++nt) {
            const int nc = ngrp * 16 + nt * 8 + qr;
            Bb[kt][nt][0] = WBu[(kt * 8 + kd * 2) * WP + nc];
            Bb[kt][nt][1] = WBu[(kt * 8 + kd * 2 + 1) * WP + nc];
        }
    }

    float bia[2][2], pww[2][2];
#pragma unroll
    for (int nt = 0; nt < 2; ++nt) {
        const int c0 = ngrp * 16 + nt * 8 + kd * 2;
        bia[nt][0] = ab_s[c0];     bia[nt][1] = ab_s[c0 + 1];
        pww[nt][0] = pw_s[c0];     pww[nt][1] = pw_s[c0 + 1];
    }

    const char* xsc = (const char*)xs;

    // ---- Phase 2: barrier-free chunked tf32 MMA (raw-f32 products, float2 loads) ----
    // Full chunks t = 0..5 cover pairs 0..767 (all valid).
    for (int t = 0; t < 6; ++t) {
        const int pb0 = t * CP + mgrp * 32 + qr;
        const uint32_t oA = offs[pb0];
        const uint32_t oB = offs[pb0 + 8];
        const uint32_t oC = offs[pb0 + 16];
        const uint32_t oD = offs[pb0 + 24];
        const char* xiA = xsc + (oA & 0xffffu); const char* xjA = xsc + (oA >> 16);
        const char* xiB = xsc + (oB & 0xffffu); const char* xjB = xsc + (oB >> 16);
        const char* xiC = xsc + (oC & 0xffffu); const char* xjC = xsc + (oC >> 16);
        const char* xiD = xsc + (oD & 0xffffu); const char* xjD = xsc + (oD >> 16);

        float acc[2][2][4];
#pragma unroll
        for (int mt = 0; mt < 2; ++mt)
#pragma unroll
            for (int nt = 0; nt < 2; ++nt) {
                acc[mt][nt][0] = bia[nt][0];
                acc[mt][nt][1] = bia[nt][1];
                acc[mt][nt][2] = bia[nt][0];
                acc[mt][nt][3] = bia[nt][1];
            }

#pragma unroll
        for (int kt = 0; kt < 8; ++kt) {
            const int db = kt * 32 + kd * 8;
            const float2 iA = *(const float2*)(xiA + db);
            const float2 jA = *(const float2*)(xjA + db);
            const float2 iB = *(const float2*)(xiB + db);
            const float2 jB = *(const float2*)(xjB + db);
            uint32_t a0 = __float_as_uint(iA.x * jA.x);
            uint32_t a2 = __float_as_uint(iA.y * jA.y);
            uint32_t a1 = __float_as_uint(iB.x * jB.x);
            uint32_t a3 = __float_as_uint(iB.y * jB.y);
            mma8(acc[0][0][0], acc[0][0][1], acc[0][0][2], acc[0][0][3],
                 a0, a1, a2, a3, Bb[kt][0][0], Bb[kt][0][1]);
            mma8(acc[0][1][0], acc[0][1][1], acc[0][1][2], acc[0][1][3],
                 a0, a1, a2, a3, Bb[kt][1][0], Bb[kt][1][1]);

            const float2 iC = *(const float2*)(xiC + db);
            const float2 jC = *(const float2*)(xjC + db);
            const float2 iD = *(const float2*)(xiD + db);
            const float2 jD = *(const float2*)(xjD + db);
            uint32_t c0 = __float_as_uint(iC.x * jC.x);
            uint32_t c2 = __float_as_uint(iC.y * jC.y);
            uint32_t c1 = __float_as_uint(iD.x * jD.x);
            uint32_t c3 = __float_as_uint(iD.y * jD.y);
            mma8(acc[1][0][0], acc[1][0][1], acc[1][0][2], acc[1][0][3],
                 c0, c1, c2, c3, Bb[kt][0][0], Bb[kt][0][1]);
            mma8(acc[1][1][0], acc[1][1][1], acc[1][1][2], acc[1][1][3],
                 c0, c1, c2, c3, Bb[kt][1][0], Bb[kt][1][1]);
        }

#pragma unroll
        for (int mt = 0; mt < 2; ++mt) {
            float lp0 = 0.f, lp1 = 0.f;
#pragma unroll
            for (int nt = 0; nt < 2; ++nt) {
                lp0 += fmaxf(acc[mt][nt][0], 0.f) * pww[nt][0] + fmaxf(acc[mt][nt][1], 0.f) * pww[nt][1];
                lp1 += fmaxf(acc[mt][nt][2], 0.f) * pww[nt][0] + fmaxf(acc[mt][nt][3], 0.f) * pww[nt][1];
            }
            lp0 += __shfl_xor_sync(0xffffffffu, lp0, 1);
            lp0 += __shfl_xor_sync(0xffffffffu, lp0, 2);
            lp1 += __shfl_xor_sync(0xffffffffu, lp1, 1);
            lp1 += __shfl_xor_sync(0xffffffffu, lp1, 2);
            if (kd == 0) {
                const int p0 = pb0 + mt * 16;
                part[p0 * 2 + ngrp]       = lp0;
                part[(p0 + 8) * 2 + ngrp] = lp1;
            }
        }
    }

    // Tail chunk: pairs 768..779 only. mgrp==0 warps (both ngrp), mt0 only.
    // Covers part slots 768..783; 780..783 are garbage but never read (p < NP).
    if (mgrp == 0) {
        const int pb0 = 6 * CP + qr;
        const uint32_t oA = offs[pb0];
        const uint32_t oB = offs[pb0 + 8];
        const char* xiA = xsc + (oA & 0xffffu); const char* xjA = xsc + (oA >> 16);
        const char* xiB = xsc + (oB & 0xffffu); const char* xjB = xsc + (oB >> 16);

        float acc[2][4];
#pragma unroll
        for (int nt = 0; nt < 2; ++nt) {
            acc[nt][0] = bia[nt][0];
            acc[nt][1] = bia[nt][1];
            acc[nt][2] = bia[nt][0];
            acc[nt][3] = bia[nt][1];
        }

#pragma unroll
        for (int kt = 0; kt < 8; ++kt) {
            const int db = kt * 32 + kd * 8;
            const float2 iA = *(const float2*)(xiA + db);
            const float2 jA = *(const float2*)(xjA + db);
            const float2 iB = *(const float2*)(xiB + db);
            const float2 jB = *(const float2*)(xjB + db);
            uint32_t a0 = __float_as_uint(iA.x * jA.x);
            uint32_t a2 = __float_as_uint(iA.y * jA.y);
            uint32_t a1 = __float_as_uint(iB.x * jB.x);
            uint32_t a3 = __float_as_uint(iB.y * jB.y);
            mma8(acc[0][0], acc[0][1], acc[0][2], acc[0][3],
                 a0, a1, a2, a3, Bb[kt][0][0], Bb[kt][0][1]);
            mma8(acc[1][0], acc[1][1], acc[1][2], acc[1][3],
                 a0, a1, a2, a3, Bb[kt][1][0], Bb[kt][1][1]);
        }

        float lp0 = 0.f, lp1 = 0.f;
#pragma unroll
        for (int nt = 0; nt < 2; ++nt) {
            lp0 += fmaxf(acc[nt][0], 0.f) * pww[nt][0] + fmaxf(acc[nt][1], 0.f) * pww[nt][1];
            lp1 += fmaxf(acc[nt][2], 0.f) * pww[nt][0] + fmaxf(acc[nt][3], 0.f) * pww[nt][1];
        }
        lp0 += __shfl_xor_sync(0xffffffffu, lp0, 1);
        lp0 += __shfl_xor_sync(0xffffffffu, lp0, 2);
        lp1 += __shfl_xor_sync(0xffffffffu, lp1, 1);
        lp1 += __shfl_xor_sync(0xffffffffu, lp1, 2);
        if (kd == 0) {
            part[pb0 * 2 + ngrp]       = lp0;
            part[(pb0 + 8) * 2 + ngrp] = lp1;
        }
    }

    // zero S (48x40)
    {
        uint4 z = make_uint4(0, 0, 0, 0);
        uint4* S4 = (uint4*)Sm;
        for (int idx = tid; idx < 48 * SP / 4; idx += THREADS) S4[idx] = z;
    }
    __syncthreads();

    // ---- Phase 3: softmax (max, exp + scatter into symmetric S) ----
    float lm = -3.4e38f;
    for (int p = tid; p < NP; p += THREADS) {
        float lg = part[p * 2] + part[p * 2 + 1] + pb;
        logits_s[p] = lg;
        lm = fmaxf(lm, lg);
    }
#pragma unroll
    for (int o = 16; o > 0; o >>= 1) lm = fmaxf(lm, __shfl_xor_sync(0xffffffffu, lm, o));
    if (lane == 0) rmax[wid] = lm;
    __syncthreads();

    float gmax = rmax[0];
#pragma unroll
    for (int wq = 1; wq < 8; ++wq) gmax = fmaxf(gmax, rmax[wq]);

    float ls = 0.f;
    for (int p = tid; p < NP; p += THREADS) {
        float e = __expf(logits_s[p] - gmax);
        ls += e;
        int rs;
        int i = row_of(p, rs);
        int j = i + 1 + (p - rs);
        float et = __uint_as_float(tf32_of(e));
        Sm[i * SP + j] = et;
        Sm[j * SP + i] = et;
    }
#pragma unroll
    for (int o = 16; o > 0; o >>= 1) ls += __shfl_xor_sync(0xffffffffu, ls, o);
    if (lane == 0) rsum[wid] = ls;
    __syncthreads();

    // ---- Phase 4: Y = S @ X via MMA; warp w = ntile w (8 dims) ----
    {
        const int w = wid;
        const int nc = w * 8 + qr;
        uint32_t Bx[5][2];
#pragma unroll
        for (int kt = 0; kt < 5; ++kt) {
            const int k0 = kt * 8 + kd * 2;
            Bx[kt][0] = tf32_of(xs[k0 * XP + nc]);
            Bx[kt][1] = tf32_of(xs[(k0 + 1) * XP + nc]);
        }
#pragma unroll
        for (int mt = 0; mt < 3; ++mt) {
            float c0 = 0.f, c1 = 0.f, c2 = 0.f, c3 = 0.f;
            const int row = mt * 16 + qr;
#pragma unroll
            for (int kt = 0; kt < 5; ++kt) {
                const int k0 = kt * 8 + kd * 2;
                const float2 sA = *(const float2*)(Sm + row * SP + k0);
                const float2 sB = *(const float2*)(Sm + (row + 8) * SP + k0);
                mma8(c0, c1, c2, c3,
                     __float_as_uint(sA.x), __float_as_uint(sB.x),
                     __float_as_uint(sA.y), __float_as_uint(sB.y),
                     Bx[kt][0], Bx[kt][1]);
            }
            *(float2*)(Ym + row * YP + w * 8 + kd * 2) = make_float2(c0, c1);
            if (mt < 2)
                *(float2*)(Ym + (row + 8) * YP + w * 8 + kd * 2) = make_float2(c2, c3);
        }
    }
    __syncthreads();

    // ---- final: attn_out[d] = 0.5 * sum_i x_i[d]*Y[i][d]; dot fc_w; /S ----
    {
        const int d = tid & 63;
        const int q = tid >> 6;
        float pa = 0.f;
#pragma unroll
        for (int i = q * 10; i < q * 10 + 10; ++i)
            pa += xs[i * XP + d] * Ym[i * YP + d];
        p4[q * 64 + d] = pa;
    }
    __syncthreads();

    if (tid < 64) {
        float v = p4[tid] + p4[64 + tid] + p4[128 + tid] + p4[192 + tid];
        red_s[tid] = 0.5f * v * fw_s[tid];
    }
    __syncthreads();

    if (tid == 0) {
        float S = 0.f;
#pragma unroll
        for (int wq = 0; wq < 8; ++wq) S += rsum[wq];
        float tt = 0.f;
#pragma unroll
        for (int k = 0; k < 64; ++k) tt += red_s[k];
        out[b] = tt / S + fc_b[0];
    }
}

extern "C" void kernel_launch(void* const* d_in, const int* in_sizes, int n_in,
                              void* d_out, int out_size)
{
    const float* x      = (const float*)d_in[0];
    const float* attn_w = (const float*)d_in[1];
    const float* attn_b = (const float*)d_in[2];
    const float* proj_w = (const float*)d_in[3];
    const float* proj_b = (const float*)d_in[4];
    const float* fc_w   = (const float*)d_in[5];
    const float* fc_b   = (const float*)d_in[6];
    float* out = (float*)d_out;

    cudaFuncSetAttribute(afm_kernel, cudaFuncAttributeMaxDynamicSharedMemorySize, SMEM_TOTAL);
    afm_kernel<<<2048, THREADS, SMEM_TOTAL>>>(x, attn_w, attn_b, proj_w, proj_b, fc_w, fc_b, out);
}